// round 10
// baseline (speedup 1.0000x reference)
#include <cuda_runtime.h>
#include <math.h>

#define B_ 2
#define S_ 2048
#define H_ 16
#define D_ 64
#define E_ 1024
#define M_ (B_*S_)

// Scratch (allocation-free)
__device__ float g_q[B_*H_*S_*D_];
__device__ float g_k[B_*H_*S_*D_];
__device__ float g_v[B_*H_*S_*D_];
__device__ float g_attn[(size_t)B_*S_*E_];
__device__ float g_cos[S_*D_];
__device__ float g_sin[S_*D_];
__device__ float g_xtf[(size_t)M_*E_];       // x, tf32-rounded
__device__ float g_wt[4*(size_t)E_*E_];      // Wq,Wk,Wv,Wo tf32-rounded

// ---------------------------------------------------------------------------
__device__ __forceinline__ unsigned f2tf(float x) {
    unsigned r;
    asm("cvt.rna.tf32.f32 %0, %1;" : "=r"(r) : "f"(x));
    return r;
}

__device__ __forceinline__ void mma_tf32(float c[4], const unsigned a[4], const unsigned b[2]) {
    asm volatile(
        "mma.sync.aligned.m16n8k8.row.col.f32.tf32.tf32.f32 "
        "{%0,%1,%2,%3},{%4,%5,%6,%7},{%8,%9},{%0,%1,%2,%3};\n"
        : "+f"(c[0]), "+f"(c[1]), "+f"(c[2]), "+f"(c[3])
        : "r"(a[0]), "r"(a[1]), "r"(a[2]), "r"(a[3]), "r"(b[0]), "r"(b[1]));
}

__device__ __forceinline__ void ldsm4(unsigned &r0, unsigned &r1, unsigned &r2, unsigned &r3,
                                      unsigned addr) {
    asm volatile("ldmatrix.sync.aligned.m8n8.x4.shared.b16 {%0,%1,%2,%3}, [%4];"
                 : "=r"(r0), "=r"(r1), "=r"(r2), "=r"(r3) : "r"(addr));
}

__device__ __forceinline__ unsigned smem_u32(const void* p) {
    return (unsigned)__cvta_generic_to_shared(p);
}

__device__ __forceinline__ void cpa16(unsigned s, const void* g) {
    asm volatile("cp.async.cg.shared.global [%0], [%1], 16;" :: "r"(s), "l"(g));
}
#define CPA_COMMIT asm volatile("cp.async.commit_group;")
#define CPA_WAIT0  asm volatile("cp.async.wait_group 0;")

// ---------------------------------------------------------------------------
// Pre-convert x and weights to tf32 bit patterns (low 13 bits zero).
// ---------------------------------------------------------------------------
__global__ void precvt_kernel(
    const float4* __restrict__ x,
    const float4* __restrict__ wq, const float4* __restrict__ wk,
    const float4* __restrict__ wv, const float4* __restrict__ wo)
{
    const int X4 = M_*E_/4;       // 1048576
    const int W4 = E_*E_/4;       // 262144
    int t = blockIdx.x * blockDim.x + threadIdx.x;
    const float4* src; float4* dst; int off;
    if (t < X4) { src = x; dst = (float4*)g_xtf; off = t; }
    else {
        int u = t - X4;
        int w = u >> 18;          // / W4
        off = u & (W4 - 1);
        src = (w == 0) ? wq : (w == 1) ? wk : (w == 2) ? wv : wo;
        dst = (float4*)(g_wt + (size_t)w * E_ * E_);
    }
    float4 v = src[off];
    float4 r;
    r.x = __uint_as_float(f2tf(v.x)); r.y = __uint_as_float(f2tf(v.y));
    r.z = __uint_as_float(f2tf(v.z)); r.w = __uint_as_float(f2tf(v.w));
    dst[off] = r;
}

// ---------------------------------------------------------------------------
__global__ void rope_table_kernel() {
    int idx = blockIdx.x * blockDim.x + threadIdx.x;
    if (idx >= S_ * D_) return;
    int sp = idx >> 6, d = idx & 63;
    float e = (float)(2 * (d & 31)) * (1.0f / 64.0f);
    float inv = powf(10000.0f, -e);
    float s, c;
    sincosf((float)sp * inv, &s, &c);
    g_cos[idx] = c;
    g_sin[idx] = s;
}

// ---------------------------------------------------------------------------
// tf32 TC GEMM, cp.async double-buffered, ldmatrix fragments.
// Inputs A,W are tf32-rounded. C[m,n] = sum_k A[m,k]*W[n,k] + bias[n]
// MODE 0: plain f32 -> out[m*E+n]
// MODE 1: RoPE, cvt -> [B,H,S,D]            (K)
// MODE 2: cvt       -> [B,H,S,D]            (V)
// MODE 3: RoPE, *0.125, cvt -> [B,H,S,D]    (Q)
// 128x128x32 tile, 256 threads (8 warps), warp tile 32x64.
// ---------------------------------------------------------------------------
template<int MODE>
__global__ __launch_bounds__(256) void gemm_tc(
    const float* __restrict__ A, const float* __restrict__ W,
    const float* __restrict__ bias, float* __restrict__ out)
{
    extern __shared__ unsigned smg[];
    unsigned (*As)[36] = (unsigned(*)[36])smg;              // [2*128][36]
    unsigned (*Bs)[36] = (unsigned(*)[36])(smg + 2*128*36); // [2*128][36]

    const int tid = threadIdx.x;
    const int lane = tid & 31, wid = tid >> 5;
    const int warp_m = wid >> 1, warp_n = wid & 1;
    const int m0 = blockIdx.y * 128, n0 = blockIdx.x * 128;
    const int lq = lane >> 2, lr = lane & 3;

    const int a_ro = (lane & 7) + ((lane >> 3) & 1) * 8;
    const int a_co = ((lane >> 4) & 1) * 4;
    const int b_ro = (lane & 7) + ((lane >> 4) & 1) * 8;
    const int b_co = ((lane >> 3) & 1) * 4;

    const unsigned as_u = smem_u32(&As[0][0]);
    const unsigned bs_u = smem_u32(&Bs[0][0]);

    const int l_row = tid >> 3;
    const int l_f   = (tid & 7) * 4;

    float c[2][8][4];
    #pragma unroll
    for (int mt = 0; mt < 2; mt++)
        #pragma unroll
        for (int nt = 0; nt < 8; nt++)
            #pragma unroll
            for (int i = 0; i < 4; i++) c[mt][nt][i] = 0.f;

    // prologue: async-copy k-tile 0 into buffer 0
    #pragma unroll
    for (int it = 0; it < 4; it++) {
        int row = l_row + it * 32;
        cpa16(as_u + ((row * 36) + l_f) * 4u, A + (size_t)(m0 + row) * E_ + l_f);
        cpa16(bs_u + ((row * 36) + l_f) * 4u, W + (size_t)(n0 + row) * E_ + l_f);
    }
    CPA_COMMIT;

    const int NKT = E_ / 32;
    for (int kt = 0; kt < NKT; kt++) {
        CPA_WAIT0;
        __syncthreads();
        if (kt + 1 < NKT) {
            int k0 = (kt + 1) * 32;
            int nxt = ((kt + 1) & 1) * 128;
            #pragma unroll
            for (int it = 0; it < 4; it++) {
                int row = l_row + it * 32;
                cpa16(as_u + (((nxt + row) * 36) + l_f) * 4u, A + (size_t)(m0 + row) * E_ + k0 + l_f);
                cpa16(bs_u + (((nxt + row) * 36) + l_f) * 4u, W + (size_t)(n0 + row) * E_ + k0 + l_f);
            }
            CPA_COMMIT;
        }
        const int cur = (kt & 1) * 128;
        const unsigned a_base = as_u + (((cur + warp_m * 32 + a_ro) * 36) + a_co) * 4u;
        const unsigned b_base = bs_u + (((cur + warp_n * 64 + b_ro) * 36) + b_co) * 4u;
        #pragma unroll
        for (int kk = 0; kk < 4; kk++) {
            int koff = kk * 8;
            unsigned afr[2][4];
            #pragma unroll
            for (int mt = 0; mt < 2; mt++)
                ldsm4(afr[mt][0], afr[mt][1], afr[mt][2], afr[mt][3],
                      a_base + (mt * 16 * 36 + koff) * 4u);
            unsigned bfr[8][2];
            #pragma unroll
            for (int p = 0; p < 4; p++) {
                unsigned r0, r1, r2, r3;
                ldsm4(r0, r1, r2, r3, b_base + (p * 16 * 36 + koff) * 4u);
                bfr[2*p][0] = r0; bfr[2*p][1] = r1;
                bfr[2*p+1][0] = r2; bfr[2*p+1][1] = r3;
            }
            #pragma unroll
            for (int mt = 0; mt < 2; mt++)
                #pragma unroll
                for (int nt = 0; nt < 8; nt++)
                    mma_tf32(c[mt][nt], afr[mt], bfr[nt]);
        }
    }

    // epilogue
    #pragma unroll
    for (int mt = 0; mt < 2; mt++) {
        #pragma unroll
        for (int rh = 0; rh < 2; rh++) {
            int m = m0 + warp_m * 32 + mt * 16 + lq + rh * 8;
            int bb = m >> 11, sp = m & (S_ - 1);
            #pragma unroll
            for (int nt = 0; nt < 8; nt++) {
                int n = n0 + warp_n * 64 + nt * 8 + lr * 2;
                float2 b2 = *(const float2*)(bias + n);
                float v0 = c[mt][nt][rh * 2]     + b2.x;
                float v1 = c[mt][nt][rh * 2 + 1] + b2.y;
                if (MODE == 0) {
                    *(float2*)(out + (size_t)m * E_ + n) = make_float2(v0, v1);
                } else {
                    int h = n >> 6, d = n & 63;
                    float o0 = v0, o1 = v1;
                    if (MODE == 1 || MODE == 3) {
                        float2 cs = *(const float2*)(g_cos + sp * D_ + d);
                        float2 sn = *(const float2*)(g_sin + sp * D_ + d);
                        o0 = v0 * cs.x - v1 * sn.x;
                        o1 = v1 * cs.y + v0 * sn.y;
                    }
                    if (MODE == 3) { o0 *= 0.125f; o1 *= 0.125f; }
                    o0 = __uint_as_float(f2tf(o0));
                    o1 = __uint_as_float(f2tf(o1));
                    size_t base = (((size_t)(bb * H_ + h)) * S_ + sp) * D_ + d;
                    *(float2*)(out + base) = make_float2(o0, o1);
                }
            }
        }
    }
}

// ---------------------------------------------------------------------------
// Flash attention, tf32 mma + ldmatrix + cp.async staging (inputs pre-tf32,
// Q pre-scaled by 1/8). 128 threads (4 warps), Q tile 64, K/V tile 64.
// ---------------------------------------------------------------------------
__global__ __launch_bounds__(128) void attn_tc(float* __restrict__ outbuf)
{
    extern __shared__ unsigned smu[];
    unsigned (*Ks)[68] = (unsigned(*)[68])smu;
    unsigned (*Vs)[68] = (unsigned(*)[68])(smu + 64*68);
    unsigned (*Ps)[68] = (unsigned(*)[68])(smu + 2*64*68);  // also Q staging

    const int tid = threadIdx.x;
    const int lane = tid & 31, wid = tid >> 5;
    const int lq = lane >> 2, lr = lane & 3;
    const int wr = wid * 16;
    const int q0 = blockIdx.x * 64;
    const int h = blockIdx.y, bb = blockIdx.z;
    const size_t head_base = ((size_t)(bb * H_ + h)) * S_ * D_;

    const int a_ro = (lane & 7) + ((lane >> 3) & 1) * 8;
    const int a_co = ((lane >> 4) & 1) * 4;
    const int b_ro = (lane & 7) + ((lane >> 4) & 1) * 8;
    const int b_co = ((lane >> 3) & 1) * 4;

    const unsigned ks_u = smem_u32(&Ks[0][0]);
    const unsigned vs_u = smem_u32(&Vs[0][0]);
    const unsigned ps_u = smem_u32(&Ps[0][0]);

    // stage Q tile (pre-scaled tf32) via cp.async, extract fragments
    #pragma unroll
    for (int it = 0; it < 8; it++) {
        int id = tid + it * 128;
        int row = id >> 4, f = (id & 15) * 4;
        cpa16(ps_u + ((row * 68) + f) * 4u,
              g_q + head_base + (size_t)(q0 + row) * D_ + f);
    }
    CPA_COMMIT;
    CPA_WAIT0;
    __syncthreads();

    const unsigned pa_base = ps_u + (((wr + a_ro) * 68) + a_co) * 4u;
    unsigned qfr[8][4];
    #pragma unroll
    for (int kk = 0; kk < 8; kk++)
        ldsm4(qfr[kk][0], qfr[kk][1], qfr[kk][2], qfr[kk][3], pa_base + (kk * 8) * 4u);
    // Ps rows [wr, wr+16) are warp-private from here on.

    float o[8][4];
    float m_i[2] = {-1e30f, -1e30f}, l_i[2] = {0.f, 0.f};
    #pragma unroll
    for (int nt = 0; nt < 8; nt++)
        #pragma unroll
        for (int i = 0; i < 4; i++) o[nt][i] = 0.f;

    for (int kt = 0; kt < S_; kt += 64) {
        __syncthreads();   // previous iteration done reading Ks/Vs
        #pragma unroll
        for (int it = 0; it < 8; it++) {
            int id = tid + it * 128;
            int row = id >> 4, f = (id & 15) * 4;
            cpa16(ks_u + ((row * 68) + f) * 4u,
                  g_k + head_base + (size_t)(kt + row) * D_ + f);
            cpa16(vs_u + ((row * 68) + f) * 4u,
                  g_v + head_base + (size_t)(kt + row) * D_ + f);
        }
        CPA_COMMIT;
        CPA_WAIT0;
        __syncthreads();

        // S = (Q/8) K^T
        float s[8][4];
        #pragma unroll
        for (int nt = 0; nt < 8; nt++)
            #pragma unroll
            for (int i = 0; i < 4; i++) s[nt][i] = 0.f;

        const unsigned kb_base = ks_u + ((b_ro * 68) + b_co) * 4u;
        #pragma unroll
        for (int kk = 0; kk < 8; kk++) {
            int koff = kk * 8;
            unsigned bfr[8][2];
            #pragma unroll
            for (int p = 0; p < 4; p++) {
                unsigned r0, r1, r2, r3;
                ldsm4(r0, r1, r2, r3, kb_base + (p * 16 * 68 + koff) * 4u);
                bfr[2*p][0] = r0; bfr[2*p][1] = r1;
                bfr[2*p+1][0] = r2; bfr[2*p+1][1] = r3;
            }
            #pragma unroll
            for (int nt = 0; nt < 8; nt++)
                mma_tf32(s[nt], qfr[kk], bfr[nt]);
        }

        // online softmax (rows: lq -> c0/c1, lq+8 -> c2/c3)
        #pragma unroll
        for (int rh = 0; rh < 2; rh++) {
            float mx = -1e30f;
            #pragma unroll
            for (int nt = 0; nt < 8; nt++)
                mx = fmaxf(mx, fmaxf(s[nt][rh*2], s[nt][rh*2+1]));
            mx = fmaxf(mx, __shfl_xor_sync(0xffffffffu, mx, 1));
            mx = fmaxf(mx, __shfl_xor_sync(0xffffffffu, mx, 2));
            float mnew = fmaxf(m_i[rh], mx);
            float corr = __expf(m_i[rh] - mnew);
            m_i[rh] = mnew;
            float sum = 0.f;
            #pragma unroll
            for (int nt = 0; nt < 8; nt++) {
                float p0 = __expf(s[nt][rh*2]   - mnew);
                float p1 = __expf(s[nt][rh*2+1] - mnew);
                s[nt][rh*2] = p0; s[nt][rh*2+1] = p1;
                sum += p0 + p1;
            }
            sum += __shfl_xor_sync(0xffffffffu, sum, 1);
            sum += __shfl_xor_sync(0xffffffffu, sum, 2);
            l_i[rh] = l_i[rh] * corr + sum;
            #pragma unroll
            for (int nt = 0; nt < 8; nt++) {
                o[nt][rh*2]   *= corr;
                o[nt][rh*2+1] *= corr;
            }
        }

        // P -> smem (warp-private rows)
        #pragma unroll
        for (int nt = 0; nt < 8; nt++) {
            int col = nt * 8 + lr * 2;
            *(uint2*)&Ps[wr + lq][col]     = make_uint2(f2tf(s[nt][0]), f2tf(s[nt][1]));
            *(uint2*)&Ps[wr + lq + 8][col] = make_uint2(f2tf(s[nt][2]), f2tf(s[nt][3]));
        }
        __syncwarp();

        // O += P V  — P A-frags via ldsm, V B-frags scalar (k-major layout)
        #pragma unroll
        for (int kk = 0; kk < 8; kk++) {
            int koff = kk * 8;
            unsigned afr[4];
            ldsm4(afr[0], afr[1], afr[2], afr[3], pa_base + koff * 4u);
            #pragma unroll
            for (int nt = 0; nt < 8; nt++) {
                unsigned bfr[2];
                bfr[0] = Vs[koff + lr][nt * 8 + lq];
                bfr[1] = Vs[koff + 4 + lr][nt * 8 + lq];
                mma_tf32(o[nt], afr, bfr);
            }
        }
    }

    // normalize + write [B,S,H,D] (tf32-rounded for the output GEMM)
    float inv0 = 1.0f / l_i[0], inv1 = 1.0f / l_i[1];
    #pragma unroll
    for (int nt = 0; nt < 8; nt++) {
        int d = nt * 8 + lr * 2;
        size_t i0 = (((size_t)bb * S_ + q0 + wr + lq) * H_ + h) * D_ + d;
        size_t i1 = (((size_t)bb * S_ + q0 + wr + lq + 8) * H_ + h) * D_ + d;
        *(float2*)(outbuf + i0) = make_float2(
            __uint_as_float(f2tf(o[nt][0] * inv0)),
            __uint_as_float(f2tf(o[nt][1] * inv0)));
        *(float2*)(outbuf + i1) = make_float2(
            __uint_as_float(f2tf(o[nt][2] * inv1)),
            __uint_as_float(f2tf(o[nt][3] * inv1)));
    }
}

// ---------------------------------------------------------------------------
extern "C" void kernel_launch(void* const* d_in, const int* in_sizes, int n_in,
                              void* d_out, int out_size)
{
    const float* x  = (const float*)d_in[0];
    const float* Wq = (const float*)d_in[1];
    const float* bq = (const float*)d_in[2];
    const float* Wk = (const float*)d_in[3];
    const float* bk = (const float*)d_in[4];
    const float* Wv = (const float*)d_in[5];
    const float* bv = (const float*)d_in[6];
    const float* Wo = (const float*)d_in[7];
    const float* bo = (const float*)d_in[8];
    float* out = (float*)d_out;

    float *pq, *pk, *pv, *pa, *pxtf, *pwt;
    cudaGetSymbolAddress((void**)&pq, g_q);
    cudaGetSymbolAddress((void**)&pk, g_k);
    cudaGetSymbolAddress((void**)&pv, g_v);
    cudaGetSymbolAddress((void**)&pa, g_attn);
    cudaGetSymbolAddress((void**)&pxtf, g_xtf);
    cudaGetSymbolAddress((void**)&pwt, g_wt);

    const int smem_gemm = 2 * 2 * 128 * 36 * sizeof(unsigned);  // 73728
    const int smem_attn = 3 * 64 * 68 * sizeof(unsigned);       // 52224
    cudaFuncSetAttribute(gemm_tc<0>, cudaFuncAttributeMaxDynamicSharedMemorySize, smem_gemm);
    cudaFuncSetAttribute(gemm_tc<1>, cudaFuncAttributeMaxDynamicSharedMemorySize, smem_gemm);
    cudaFuncSetAttribute(gemm_tc<2>, cudaFuncAttributeMaxDynamicSharedMemorySize, smem_gemm);
    cudaFuncSetAttribute(gemm_tc<3>, cudaFuncAttributeMaxDynamicSharedMemorySize, smem_gemm);
    cudaFuncSetAttribute(attn_tc,    cudaFuncAttributeMaxDynamicSharedMemorySize, smem_attn);

    // pre-pass: tf32-round x and weights; build RoPE table
    const int total4 = (M_*E_ + 4*E_*E_) / 4;   // 2097152
    precvt_kernel<<<total4 / 256, 256>>>(
        (const float4*)x, (const float4*)Wq, (const float4*)Wk,
        (const float4*)Wv, (const float4*)Wo);
    rope_table_kernel<<<(S_*D_ + 255)/256, 256>>>();

    dim3 gg(E_/128, M_/128);   // (8, 32)
    gemm_tc<3><<<gg, 256, smem_gemm>>>(pxtf, pwt + 0*(size_t)E_*E_, bq, pq);
    gemm_tc<1><<<gg, 256, smem_gemm>>>(pxtf, pwt + 1*(size_t)E_*E_, bk, pk);
    gemm_tc<2><<<gg, 256, smem_gemm>>>(pxtf, pwt + 2*(size_t)E_*E_, bv, pv);
    attn_tc<<<dim3(S_/64, H_, B_), 128, smem_attn>>>(pa);
    gemm_tc<0><<<gg, 256, smem_gemm>>>(pa, pwt + 3*(size_t)E_*E_, bo, out);
}